// round 1
// baseline (speedup 1.0000x reference)
#include <cuda_runtime.h>
#include <stdint.h>

// ---------------------------------------------------------------------------
// Transfer_35399120453953:
//   gathered    = features[atom_indices]            [E, 64]
//   transferred = segment_sum(gathered, domain_ids) [M, 64]   (domain_ids sorted)
//   out         = transferred @ W + b               [M, 128]
//
// Inputs (metadata order):
//   d_in[0] features      f32  [N_ATOMS*64]
//   d_in[1] atom_indices  i64 or i32 (JAX x64 may be off) [E]
//   d_in[2] domain_ids    i64 or i32, sorted             [E]
//   d_in[3] num_domains   scalar (unused; M = out_size/128)
//   d_in[4] W             f32  [64*128]
//   d_in[5] b             f32  [128]
// ---------------------------------------------------------------------------

#define C_IN   64
#define C_OUT  128
#define WARPS_PER_BLOCK 8
#define DOMS_PER_WARP   4
#define DOMS_PER_BLOCK  (WARPS_PER_BLOCK * DOMS_PER_WARP)

// scratch: segment start offsets (sized generously; M=250000 in this problem)
__device__ int g_offsets[1048577];
__device__ int g_is64;

// ---------------------------------------------------------------------------
// Kernel 0: detect whether index arrays are int64 or int32.
// If int64 little-endian, every odd 32-bit word (high half) of the first
// entries is 0 (indices < 2^32). If int32, those words are random indices
// in [0, N_ATOMS) -> all-zero probability ~0.
// ---------------------------------------------------------------------------
__global__ void detect_dtype_kernel(const void* atom_indices) {
    const int* p = (const int*)atom_indices;
    int all_zero = 1;
    #pragma unroll
    for (int k = 0; k < 16; k++) {
        if (p[2 * k + 1] != 0) all_zero = 0;
    }
    g_is64 = all_zero;
}

__device__ __forceinline__ long long load_index(const void* p, long long e, int is64) {
    if (is64) return ((const long long*)p)[e];
    return (long long)((const int*)p)[e];
}

// ---------------------------------------------------------------------------
// Kernel 1: offsets[d] = lower_bound(domain_ids, d) for d in [0, M]
// ---------------------------------------------------------------------------
__global__ void compute_offsets_kernel(const void* domain_ids, int E, int M) {
    int d = blockIdx.x * blockDim.x + threadIdx.x;
    if (d > M) return;
    int is64 = g_is64;
    int lo = 0, hi = E;
    while (lo < hi) {
        int mid = (lo + hi) >> 1;
        long long v = load_index(domain_ids, (long long)mid, is64);
        if (v < (long long)d) lo = mid + 1; else hi = mid;
    }
    g_offsets[d] = lo;
}

// ---------------------------------------------------------------------------
// Kernel 2: fused gather + segment-sum + [1,64]x[64,128] projection.
// One warp handles DOMS_PER_WARP=4 consecutive domains:
//   phase 1: lanes hold channels (2 per lane, float2), iterate the domain's
//            contiguous entry run, gather 256B feature rows (coalesced).
//   phase 2: sums staged to smem; each lane produces 4 output columns,
//            W read from smem as float4 (conflict-free), amortized over
//            the 4 batched domains.
// ---------------------------------------------------------------------------
__global__ __launch_bounds__(WARPS_PER_BLOCK * 32)
void transfer_fused_kernel(const float* __restrict__ features,
                           const void* __restrict__ atom_indices,
                           const float* __restrict__ W,
                           const float* __restrict__ b,
                           float* __restrict__ out,
                           int M) {
    __shared__ float Ws[C_IN * C_OUT];                       // 32 KB
    __shared__ float bs[C_OUT];                              // 512 B
    __shared__ float sums[WARPS_PER_BLOCK][DOMS_PER_WARP][C_IN]; // 8 KB

    const int tid  = threadIdx.x;
    const int warp = tid >> 5;
    const int lane = tid & 31;

    // stage W and b
    #pragma unroll
    for (int i = tid; i < C_IN * C_OUT; i += WARPS_PER_BLOCK * 32)
        Ws[i] = W[i];
    if (tid < C_OUT) bs[tid] = b[tid];
    __syncthreads();

    const int is64 = g_is64;
    const int dbase = (blockIdx.x * WARPS_PER_BLOCK + warp) * DOMS_PER_WARP;
    if (dbase >= M) return;

    // ---- phase 1: per-domain segment sums (lane = 2 channels, float2) ----
    #pragma unroll
    for (int g = 0; g < DOMS_PER_WARP; g++) {
        const int d = dbase + g;
        float2 acc = make_float2(0.f, 0.f);
        if (d < M) {
            const int s0 = g_offsets[d];
            const int s1 = g_offsets[d + 1];
            #pragma unroll 4
            for (int e = s0; e < s1; e++) {
                const long long a = load_index(atom_indices, (long long)e, is64);
                const float2 v =
                    __ldg(((const float2*)(features + a * C_IN)) + lane);
                acc.x += v.x;
                acc.y += v.y;
            }
        }
        ((float2*)&sums[warp][g][0])[lane] = acc;
    }
    __syncwarp();

    // ---- phase 2: out[d][j] = b[j] + sum_c sums[d][c] * W[c][j] ----
    // lane covers columns j = lane*4 .. lane*4+3 (float4)
    const float4* Ws4 = (const float4*)Ws;
    const float4  bv  = ((const float4*)bs)[lane];

    float4 o[DOMS_PER_WARP];
    #pragma unroll
    for (int g = 0; g < DOMS_PER_WARP; g++) o[g] = bv;

    #pragma unroll 8
    for (int c = 0; c < C_IN; c++) {
        const float4 w = Ws4[c * (C_OUT / 4) + lane];
        #pragma unroll
        for (int g = 0; g < DOMS_PER_WARP; g++) {
            const float s = sums[warp][g][c];  // smem broadcast
            o[g].x = fmaf(s, w.x, o[g].x);
            o[g].y = fmaf(s, w.y, o[g].y);
            o[g].z = fmaf(s, w.z, o[g].z);
            o[g].w = fmaf(s, w.w, o[g].w);
        }
    }

    #pragma unroll
    for (int g = 0; g < DOMS_PER_WARP; g++) {
        const int d = dbase + g;
        if (d < M)
            ((float4*)(out + (long long)d * C_OUT))[lane] = o[g];
    }
}

// ---------------------------------------------------------------------------
extern "C" void kernel_launch(void* const* d_in, const int* in_sizes, int n_in,
                              void* d_out, int out_size) {
    const float* features     = (const float*)d_in[0];
    const void*  atom_indices = d_in[1];
    const void*  domain_ids   = d_in[2];
    const float* W            = (const float*)d_in[4];
    const float* b            = (const float*)d_in[5];
    float*       out          = (float*)d_out;

    const int E = in_sizes[1];          // entry count (dtype-independent)
    const int M = out_size / C_OUT;     // number of domains

    detect_dtype_kernel<<<1, 1>>>(atom_indices);

    const int off_threads = 256;
    const int off_blocks  = (M + 1 + off_threads - 1) / off_threads;
    compute_offsets_kernel<<<off_blocks, off_threads>>>(domain_ids, E, M);

    const int blocks = (M + DOMS_PER_BLOCK - 1) / DOMS_PER_BLOCK;
    transfer_fused_kernel<<<blocks, WARPS_PER_BLOCK * 32>>>(
        features, atom_indices, W, b, out, M);
}

// round 2
// speedup vs baseline: 1.0973x; 1.0973x over previous
#include <cuda_runtime.h>
#include <stdint.h>

// ---------------------------------------------------------------------------
// Transfer_35399120453953:
//   gathered    = features[atom_indices]            [E, 64]
//   transferred = segment_sum(gathered, domain_ids) [M, 64]   (domain_ids sorted)
//   out         = transferred @ W + b               [M, 128]
//
// Inputs (metadata order):
//   d_in[0] features      f32  [N_ATOMS*64]
//   d_in[1] atom_indices  i64 or i32 (JAX x64 may be off) [E]
//   d_in[2] domain_ids    same dtype as atom_indices, sorted [E]
//   d_in[3] num_domains   scalar (unused; M = out_size/128)
//   d_in[4] W             f32  [64*128]
//   d_in[5] b             f32  [128]
// ---------------------------------------------------------------------------

#define C_IN   64
#define C_OUT  128
#define WARPS_PER_BLOCK 8
#define DOMS_PER_WARP   4
#define DOMS_PER_BLOCK  (WARPS_PER_BLOCK * DOMS_PER_WARP)

// scratch: segment start offsets (M=250000 here; sized generously)
__device__ int g_offsets[1048577];

// ---------------------------------------------------------------------------
// Inline dtype sniff: int64 little-endian => high word of each of the first
// 16 entries is 0 (indices < 2^32). atom_indices is random in [0, N_ATOMS),
// so for int32 data the odd words are random nonzero with overwhelming
// probability. (Never sniff domain_ids: it is sorted and starts near 0.)
// All 16 loads hit the same cached lines -> effectively free per thread.
// ---------------------------------------------------------------------------
__device__ __forceinline__ int detect_is64(const void* p_) {
    const int* p = (const int*)p_;
    int all_zero = 1;
    #pragma unroll
    for (int k = 0; k < 16; k++) all_zero &= (p[2 * k + 1] == 0);
    return all_zero;
}

__device__ __forceinline__ long long load_index(const void* p, long long e, int is64) {
    if (is64) return ((const long long*)p)[e];
    return (long long)((const int*)p)[e];
}

// ---------------------------------------------------------------------------
// Kernel 1: offsets[d] = lower_bound(domain_ids, d) for d in [0, M]
// ---------------------------------------------------------------------------
__global__ void compute_offsets_kernel(const void* __restrict__ domain_ids,
                                       const void* __restrict__ atom_indices,
                                       int E, int M) {
    const int is64 = detect_is64(atom_indices);
    int d = blockIdx.x * blockDim.x + threadIdx.x;
    if (d > M) return;
    int lo = 0, hi = E;
    while (lo < hi) {
        int mid = (lo + hi) >> 1;
        long long v = load_index(domain_ids, (long long)mid, is64);
        if (v < (long long)d) lo = mid + 1; else hi = mid;
    }
    g_offsets[d] = lo;
}

// ---------------------------------------------------------------------------
// Kernel 2: fused gather + segment-sum + [64]x[64,128] projection.
// One warp handles 4 consecutive domains.
//   phase 1: 16 lanes x float4 per feature row -> each warp load covers TWO
//            rows (512 B, fully coalesced). Halves (even/odd entries) are
//            combined with 4 shfl_xor(16). Unroll 4 => 8 rows (2 KB) in
//            flight per warp.
//   phase 2: sums staged in smem; lane j produces output columns 4j..4j+3
//            via float4 W reads from smem (conflict-free), amortized over
//            the 4 batched domains.
// ---------------------------------------------------------------------------
__global__ __launch_bounds__(WARPS_PER_BLOCK * 32)
void transfer_fused_kernel(const float* __restrict__ features,
                           const void* __restrict__ atom_indices,
                           const float* __restrict__ W,
                           const float* __restrict__ b,
                           float* __restrict__ out,
                           int M) {
    __shared__ float Ws[C_IN * C_OUT];                           // 32 KB
    __shared__ float bs[C_OUT];                                  // 512 B
    __shared__ float sums[WARPS_PER_BLOCK][DOMS_PER_WARP][C_IN]; // 8 KB

    const int tid  = threadIdx.x;
    const int warp = tid >> 5;
    const int lane = tid & 31;

    // stage W and b
    #pragma unroll
    for (int i = tid; i < C_IN * C_OUT; i += WARPS_PER_BLOCK * 32)
        Ws[i] = W[i];
    if (tid < C_OUT) bs[tid] = b[tid];
    __syncthreads();

    const int is64  = detect_is64(atom_indices);
    const int dbase = (blockIdx.x * WARPS_PER_BLOCK + warp) * DOMS_PER_WARP;
    if (dbase >= M) return;

    const int half = lane >> 4;   // 0: even entries, 1: odd entries
    const int l16  = lane & 15;   // channel group: floats 4*l16 .. 4*l16+3

    // ---- phase 1: per-domain segment sums ----
    #pragma unroll
    for (int g = 0; g < DOMS_PER_WARP; g++) {
        const int d = dbase + g;
        float4 acc = make_float4(0.f, 0.f, 0.f, 0.f);
        if (d < M) {
            const int s0 = g_offsets[d];
            const int s1 = g_offsets[d + 1];
            #pragma unroll 4
            for (int e = s0 + half; e < s1; e += 2) {
                const long long a = load_index(atom_indices, (long long)e, is64);
                const float4 v =
                    __ldg(((const float4*)(features + a * C_IN)) + l16);
                acc.x += v.x; acc.y += v.y; acc.z += v.z; acc.w += v.w;
            }
        }
        // combine even/odd halves
        acc.x += __shfl_xor_sync(0xffffffffu, acc.x, 16);
        acc.y += __shfl_xor_sync(0xffffffffu, acc.y, 16);
        acc.z += __shfl_xor_sync(0xffffffffu, acc.z, 16);
        acc.w += __shfl_xor_sync(0xffffffffu, acc.w, 16);
        if (half == 0)
            ((float4*)&sums[warp][g][0])[l16] = acc;
    }
    __syncwarp();

    // ---- phase 2: out[d][j] = b[j] + sum_c sums[d][c] * W[c][j] ----
    const float4* Ws4 = (const float4*)Ws;
    const float4  bv  = ((const float4*)bs)[lane];

    float4 o[DOMS_PER_WARP];
    #pragma unroll
    for (int g = 0; g < DOMS_PER_WARP; g++) o[g] = bv;

    #pragma unroll 8
    for (int c = 0; c < C_IN; c++) {
        const float4 w = Ws4[c * (C_OUT / 4) + lane];
        #pragma unroll
        for (int g = 0; g < DOMS_PER_WARP; g++) {
            const float s = sums[warp][g][c];  // smem broadcast
            o[g].x = fmaf(s, w.x, o[g].x);
            o[g].y = fmaf(s, w.y, o[g].y);
            o[g].z = fmaf(s, w.z, o[g].z);
            o[g].w = fmaf(s, w.w, o[g].w);
        }
    }

    #pragma unroll
    for (int g = 0; g < DOMS_PER_WARP; g++) {
        const int d = dbase + g;
        if (d < M)
            ((float4*)(out + (long long)d * C_OUT))[lane] = o[g];
    }
}

// ---------------------------------------------------------------------------
extern "C" void kernel_launch(void* const* d_in, const int* in_sizes, int n_in,
                              void* d_out, int out_size) {
    const float* features     = (const float*)d_in[0];
    const void*  atom_indices = d_in[1];
    const void*  domain_ids   = d_in[2];
    const float* W            = (const float*)d_in[4];
    const float* b            = (const float*)d_in[5];
    float*       out          = (float*)d_out;

    const int E = in_sizes[1];          // entry count (dtype-independent? no:
                                        // element count per harness metadata)
    const int M = out_size / C_OUT;     // number of domains

    const int off_threads = 256;
    const int off_blocks  = (M + 1 + off_threads - 1) / off_threads;
    compute_offsets_kernel<<<off_blocks, off_threads>>>(domain_ids, atom_indices, E, M);

    const int blocks = (M + DOMS_PER_BLOCK - 1) / DOMS_PER_BLOCK;
    transfer_fused_kernel<<<blocks, WARPS_PER_BLOCK * 32>>>(
        features, atom_indices, W, b, out, M);
}